// round 2
// baseline (speedup 1.0000x reference)
#include <cuda_runtime.h>
#include <math.h>

#define Bdim 2
#define Nseq 1536
#define Dmod 1024
#define Hn   16
#define DHd  64
#define SCALE 0.125f
#define ROWS (Bdim * Nseq)          // 3072
#define OUT_ELEMS ((size_t)ROWS * Dmod)  // 3145728

// scratch (no cudaMalloc allowed)
__device__ float g_Q [ROWS * Dmod];
__device__ float g_K [ROWS * Dmod];
__device__ float g_V [ROWS * Dmod];
__device__ float g_H1[ROWS * Dmod];
__device__ float g_AT[ROWS * Dmod];
__device__ float g_gate[ROWS];

// ---------------------------------------------------------------------------
// Generic tiled fp32 GEMM: C[M,N] = A[M,K] @ W[K,N] + bias, optional exact GELU
// 64x64 tile, k-tile 16, 256 threads, 4x4 per thread.
// ---------------------------------------------------------------------------
__global__ void __launch_bounds__(256)
gemm_bias_act(const float* __restrict__ A,
              const float* __restrict__ W,
              const float* __restrict__ bias,
              float* __restrict__ C,
              int M, int N, int K, int act)
{
    __shared__ float As[16][64];   // transposed: As[k][m]
    __shared__ float Ws[16][64];   // Ws[k][n]

    const int tid = threadIdx.x;
    const int tx = tid & 15;
    const int ty = tid >> 4;
    const int m0 = blockIdx.y * 64;
    const int n0 = blockIdx.x * 64;

    const int ar = tid >> 2;          // 0..63  (A tile row)
    const int ac = (tid & 3) << 2;    // 0,4,8,12 (A tile col, float4)
    const int wr = tid >> 4;          // 0..15  (W tile row)
    const int wc = (tid & 15) << 2;   // 0..60  (W tile col, float4)

    float acc[4][4] = {};

    for (int k0 = 0; k0 < K; k0 += 16) {
        float4 av = *(const float4*)(A + (size_t)(m0 + ar) * K + k0 + ac);
        float4 wv = *(const float4*)(W + (size_t)(k0 + wr) * N + n0 + wc);
        __syncthreads();
        As[ac + 0][ar] = av.x;
        As[ac + 1][ar] = av.y;
        As[ac + 2][ar] = av.z;
        As[ac + 3][ar] = av.w;
        *(float4*)&Ws[wr][wc] = wv;
        __syncthreads();

#pragma unroll
        for (int kk = 0; kk < 16; kk++) {
            float4 a4 = *(const float4*)&As[kk][ty << 2];
            float4 b4 = *(const float4*)&Ws[kk][tx << 2];
            float av_[4] = {a4.x, a4.y, a4.z, a4.w};
            float bv_[4] = {b4.x, b4.y, b4.z, b4.w};
#pragma unroll
            for (int i = 0; i < 4; i++)
#pragma unroll
                for (int j = 0; j < 4; j++)
                    acc[i][j] += av_[i] * bv_[j];
        }
    }

#pragma unroll
    for (int i = 0; i < 4; i++) {
        int m = m0 + (ty << 2) + i;
#pragma unroll
        for (int j = 0; j < 4; j++) {
            int n = n0 + (tx << 2) + j;
            float v = acc[i][j] + bias[n];
            if (act == 1)
                v = 0.5f * v * (1.0f + erff(v * 0.70710678118654752f));
            C[(size_t)m * N + n] = v;
        }
    }
}

// ---------------------------------------------------------------------------
// gate[row] = sigmoid(dot(H1[row,:], Wg2) + bg2)
// ---------------------------------------------------------------------------
__global__ void __launch_bounds__(256)
gate_kernel(const float* __restrict__ H1,
            const float* __restrict__ Wg2,
            const float* __restrict__ bg2,
            float* __restrict__ gate)
{
    __shared__ float red[8];
    const int row = blockIdx.x;
    const float* hp = H1 + (size_t)row * Dmod;
    float loc = 0.f;
    for (int k = threadIdx.x; k < Dmod; k += blockDim.x)
        loc += hp[k] * Wg2[k];
#pragma unroll
    for (int o = 16; o > 0; o >>= 1)
        loc += __shfl_xor_sync(0xffffffffu, loc, o);
    const int w = threadIdx.x >> 5;
    if ((threadIdx.x & 31) == 0) red[w] = loc;
    __syncthreads();
    if (threadIdx.x == 0) {
        float s = 0.f;
        for (int i = 0; i < 8; i++) s += red[i];
        gate[row] = 1.f / (1.f + expf(-(s + bg2[0])));
    }
}

// ---------------------------------------------------------------------------
// block reductions for 128 threads (4 warps)
// ---------------------------------------------------------------------------
__device__ __forceinline__ float bred_max(float v, float* red)
{
#pragma unroll
    for (int o = 16; o > 0; o >>= 1)
        v = fmaxf(v, __shfl_xor_sync(0xffffffffu, v, o));
    if ((threadIdx.x & 31) == 0) red[threadIdx.x >> 5] = v;
    __syncthreads();
    float r = fmaxf(fmaxf(red[0], red[1]), fmaxf(red[2], red[3]));
    __syncthreads();
    return r;
}

__device__ __forceinline__ float bred_sum(float v, float* red)
{
#pragma unroll
    for (int o = 16; o > 0; o >>= 1)
        v += __shfl_xor_sync(0xffffffffu, v, o);
    if ((threadIdx.x & 31) == 0) red[threadIdx.x >> 5] = v;
    __syncthreads();
    float r = red[0] + red[1] + red[2] + red[3];
    __syncthreads();
    return r;
}

// ---------------------------------------------------------------------------
// One block per (b, h, q) query row. 128 threads.
//   pass 1: scores  s_j = (q . k_j) * SCALE   (causal: j <= q)
//   softmax + exact entropy with log(p + 1e-6)
//   pass 2: out_d = gate * sum_j p_j V[j][d]
// ---------------------------------------------------------------------------
#define KV_STRIDE 65   // padded row stride (bank-conflict-free)

__global__ void __launch_bounds__(128)
attn_kernel(const float* __restrict__ gate,
            float* __restrict__ entropy_out)
{
    __shared__ float qs[64];
    __shared__ float sc[Nseq];
    __shared__ float kv[128 * KV_STRIDE];
    __shared__ float red[4];
    __shared__ float red2[64];

    const int bid = blockIdx.x;
    const int q = bid % Nseq;
    const int h = (bid / Nseq) % Hn;
    const int b = bid / (Nseq * Hn);
    const int tid = threadIdx.x;

    const size_t headoff = (size_t)b * Nseq * Dmod + (size_t)h * DHd;

    if (tid < 64)
        qs[tid] = g_Q[headoff + (size_t)q * Dmod + tid];
    const int nk = q + 1;

    // ---- pass 1: scores ----
    for (int t0 = 0; t0 < nk; t0 += 128) {
        const int tn = min(128, nk - t0);
        __syncthreads();
        for (int idx = tid; idx < tn * 16; idx += 128) {
            int r = idx >> 4;
            int c = (idx & 15) << 2;
            float4 v = *(const float4*)(g_K + headoff + (size_t)(t0 + r) * Dmod + c);
            int sb = r * KV_STRIDE + c;
            kv[sb + 0] = v.x; kv[sb + 1] = v.y; kv[sb + 2] = v.z; kv[sb + 3] = v.w;
        }
        __syncthreads();
        for (int j = tid; j < tn; j += 128) {
            float s = 0.f;
            const float* kr = &kv[j * KV_STRIDE];
#pragma unroll
            for (int d = 0; d < 64; d++)
                s += qs[d] * kr[d];
            sc[t0 + j] = s * SCALE;
        }
    }
    __syncthreads();

    // ---- softmax ----
    float m = -1e30f;
    for (int j = tid; j < nk; j += 128) m = fmaxf(m, sc[j]);
    m = bred_max(m, red);

    float lsum = 0.f;
    for (int j = tid; j < nk; j += 128) {
        float e = expf(sc[j] - m);
        sc[j] = e;
        lsum += e;
    }
    const float l = bred_sum(lsum, red);
    const float inv_l = 1.f / l;

    // ---- entropy: -(sum p * log(p + 1e-6)) ----
    float eloc = 0.f;
    for (int j = tid; j < nk; j += 128) {
        float p = sc[j] * inv_l;
        eloc += p * logf(p + 1e-6f);
    }
    const float esum = bred_sum(eloc, red);
    if (tid == 0)
        entropy_out[((size_t)b * Hn + h) * Nseq + q] = -esum;

    // ---- pass 2: out = (p @ V) * inv_l * gate ----
    const int d = tid & 63;
    const int part = tid >> 6;
    float accv = 0.f;
    for (int t0 = 0; t0 < nk; t0 += 128) {
        const int tn = min(128, nk - t0);
        __syncthreads();
        for (int idx = tid; idx < tn * 16; idx += 128) {
            int r = idx >> 4;
            int c = (idx & 15) << 2;
            float4 v = *(const float4*)(g_V + headoff + (size_t)(t0 + r) * Dmod + c);
            int sb = r * KV_STRIDE + c;
            kv[sb + 0] = v.x; kv[sb + 1] = v.y; kv[sb + 2] = v.z; kv[sb + 3] = v.w;
        }
        __syncthreads();
        for (int jl = part; jl < tn; jl += 2)
            accv += sc[t0 + jl] * kv[jl * KV_STRIDE + d];
    }
    __syncthreads();
    if (part == 1) red2[d] = accv;
    __syncthreads();
    if (part == 0) {
        float tot = (accv + red2[d]) * inv_l * gate[b * Nseq + q];
        g_AT[headoff + (size_t)q * Dmod + d] = tot;
    }
}

// ---------------------------------------------------------------------------
extern "C" void kernel_launch(void* const* d_in, const int* in_sizes, int n_in,
                              void* d_out, int out_size)
{
    const float* x   = (const float*)d_in[0];
    // d_in[1] = attn_bias (exact causal prior; handled analytically by loop bound)
    const float* Wq  = (const float*)d_in[2];
    const float* bq  = (const float*)d_in[3];
    const float* Wk  = (const float*)d_in[4];
    const float* bk  = (const float*)d_in[5];
    const float* Wv  = (const float*)d_in[6];
    const float* bv  = (const float*)d_in[7];
    const float* Wg1 = (const float*)d_in[8];
    const float* bg1 = (const float*)d_in[9];
    const float* Wg2 = (const float*)d_in[10];
    const float* bg2 = (const float*)d_in[11];
    const float* Wo  = (const float*)d_in[12];
    const float* bo  = (const float*)d_in[13];

    float* out = (float*)d_out;

    float *Qp, *Kp, *Vp, *H1p, *ATp, *gp;
    cudaGetSymbolAddress((void**)&Qp,  g_Q);
    cudaGetSymbolAddress((void**)&Kp,  g_K);
    cudaGetSymbolAddress((void**)&Vp,  g_V);
    cudaGetSymbolAddress((void**)&H1p, g_H1);
    cudaGetSymbolAddress((void**)&ATp, g_AT);
    cudaGetSymbolAddress((void**)&gp,  g_gate);

    dim3 gg(Dmod / 64, ROWS / 64);   // (16, 48)
    dim3 gb(256);

    gemm_bias_act<<<gg, gb>>>(x, Wq,  bq,  Qp,  ROWS, Dmod, Dmod, 0);
    gemm_bias_act<<<gg, gb>>>(x, Wk,  bk,  Kp,  ROWS, Dmod, Dmod, 0);
    gemm_bias_act<<<gg, gb>>>(x, Wv,  bv,  Vp,  ROWS, Dmod, Dmod, 0);
    gemm_bias_act<<<gg, gb>>>(x, Wg1, bg1, H1p, ROWS, Dmod, Dmod, 1);

    gate_kernel<<<ROWS, 256>>>(H1p, Wg2, bg2, gp);

    attn_kernel<<<Bdim * Hn * Nseq, 128>>>(gp, out + OUT_ELEMS);

    gemm_bias_act<<<gg, gb>>>(ATp, Wo, bo, out, ROWS, Dmod, Dmod, 0);
}